// round 16
// baseline (speedup 1.0000x reference)
#include <cuda_runtime.h>
#include <cuda_bf16.h>
#include <cstdint>
#include <math.h>

#define NEGV 1000000000000.0f

// ---------------- scratch (static device globals; no allocs) ----------------
__device__ __align__(16) unsigned char g_w1b[768 * 128 * 2];  // W1 bf16 row-major
__device__ __align__(16) unsigned char g_qb[4 * 1024 * 64 * 2]; // q bf16 [b][m][d], pre-scaled 1/8
__device__ __align__(16) unsigned char g_kb[4 * 64 * 1024 * 2]; // k bf16 [b][d][n]
__device__ float g_bA[4 * 16 * 1024];    // bias[b, n, 2o]/2   -> indexed [b][o][n]
__device__ float g_bB[4 * 16 * 1024];    // bias[b, m, 2o+1]/2 -> indexed [b][o][m]
__device__ int g_arrive = 0;             // grid barrier (self-resetting)
__device__ int g_depart = 0;

// ---------------- packed f32x2 helpers ----------------
__device__ __forceinline__ unsigned long long pk2(float lo, float hi) {
    unsigned long long r;
    asm("mov.b64 %0, {%1,%2};" : "=l"(r) : "f"(lo), "f"(hi));
    return r;
}
__device__ __forceinline__ unsigned long long fma2n(unsigned long long a,
                                                    unsigned long long b,
                                                    unsigned long long c) {
    unsigned long long d;
    asm("fma.rn.f32x2 %0, %1, %2, %3;" : "=l"(d) : "l"(a), "l"(b), "l"(c));
    return d;
}
__device__ __forceinline__ unsigned long long add2(unsigned long long a,
                                                   unsigned long long b) {
    unsigned long long d;
    asm("add.rn.f32x2 %0, %1, %2;" : "=l"(d) : "l"(a), "l"(b));
    return d;
}
__device__ __forceinline__ float2 up2(unsigned long long v) {
    float2 r;
    asm("mov.b64 {%0,%1}, %2;" : "=f"(r.x), "=f"(r.y) : "l"(v));
    return r;
}
__device__ __forceinline__ void cp_async16(void* smem_dst, const void* gsrc) {
    unsigned saddr = (unsigned)__cvta_generic_to_shared(smem_dst);
    asm volatile("cp.async.ca.shared.global [%0], [%1], 16;\n"
                 :: "r"(saddr), "l"(gsrc) : "memory");
}
__device__ __forceinline__ uint32_t packbf2(float a, float b) {
    __nv_bfloat162 v = __floats2bfloat162_rn(a, b);
    return *(uint32_t*)&v;
}
__device__ __forceinline__ void ldsm_x4(uint32_t& r0, uint32_t& r1, uint32_t& r2,
                                        uint32_t& r3, uint32_t addr) {
    asm volatile("ldmatrix.sync.aligned.m8n8.x4.shared.b16 {%0,%1,%2,%3}, [%4];"
                 : "=r"(r0), "=r"(r1), "=r"(r2), "=r"(r3) : "r"(addr));
}
__device__ __forceinline__ void ldsm_x4t(uint32_t& r0, uint32_t& r1, uint32_t& r2,
                                         uint32_t& r3, uint32_t addr) {
    asm volatile("ldmatrix.sync.aligned.m8n8.x4.trans.shared.b16 {%0,%1,%2,%3}, [%4];"
                 : "=r"(r0), "=r"(r1), "=r"(r2), "=r"(r3) : "r"(addr));
}
__device__ __forceinline__ void mma_bf16(float* d, uint32_t a0, uint32_t a1,
                                         uint32_t a2, uint32_t a3, uint32_t b0,
                                         uint32_t b1) {
    asm volatile(
        "mma.sync.aligned.m16n8k16.row.col.f32.bf16.bf16.f32 "
        "{%0,%1,%2,%3}, {%4,%5,%6,%7}, {%8,%9}, {%0,%1,%2,%3};"
        : "+f"(d[0]), "+f"(d[1]), "+f"(d[2]), "+f"(d[3])
        : "r"(a0), "r"(a1), "r"(a2), "r"(a3), "r"(b0), "r"(b1));
}

// ---------------- kernel 1 (fused): W1 convert + barrier + GEMM + RoPE ------
// 128 blocks (32 rows), 256 thr (8 warps). All 128 blocks are co-resident
// (41.6KB smem, <=148 SMs), so the arrive/depart grid barrier cannot deadlock.
// Each block converts 768 W1 elements to bf16; barrier; then the proven R14
// mainloop + epilogue run unchanged.
__global__ __launch_bounds__(256) void k1_kernel(
    const float* __restrict__ x, const float* __restrict__ W1,
    const float* __restrict__ b1, const float* __restrict__ W2,
    const float* __restrict__ b2) {
    __shared__ __align__(16) unsigned char smem[41600];
    const uint32_t sbase = (uint32_t)__cvta_generic_to_shared(smem);
    float* b1s = (float*)(smem + 40960);
    float* invf_s = (float*)(smem + 41472);

    const int tid = threadIdx.x;
    const int lane = tid & 31;
    const int warp = tid >> 5;
    const int row0 = blockIdx.x * 32;

    // ---- phase 0: convert this block's W1 slice to bf16 ----
    if (tid < 192) {
        int i = blockIdx.x * 768 + tid * 4;
        float4 v = *(const float4*)(W1 + i);
        uint2 p;
        p.x = packbf2(v.x, v.y);
        p.y = packbf2(v.z, v.w);
        *(uint2*)(g_w1b + (size_t)i * 2) = p;
    }

    if (tid < 128) b1s[tid] = b1[tid];
    else if (tid < 160) {
        int j = tid - 128;
        invf_s[j] = (float)exp(-(double)j * (9.210340371976184 / 32.0));
    }

    // ---- grid barrier (self-resetting for graph replays) ----
    __threadfence();
    __syncthreads();
    if (tid == 0) {
        atomicAdd(&g_arrive, 1);
        while (atomicAdd(&g_arrive, 0) < 128) { }
        int d = atomicAdd(&g_depart, 1) + 1;
        if (d == 128) {           // last departer resets both counters
            atomicExch(&g_depart, 0);
            atomicExch(&g_arrive, 0);
        }
    }
    __syncthreads();
    __threadfence();

    // A staging map: thread -> one 16B chunk (8 bf16) of the 32x64 tile
    const int As_row = tid >> 3;       // 0..31
    const int As_kc = tid & 7;         // 0..7
    const int As_csw = (As_kc ^ (As_row & 7)) & 7;
    const float* xr = x + (size_t)(row0 + As_row) * 768 + As_kc * 8;

    // ---- prologue: stage kt=0 ----
    {
#pragma unroll
        for (int i = 0; i < 4; i++) {
            int c = tid + 256 * i;             // 1024 chunks
            int row = c >> 4, nc = c & 15;
            int csw = (nc & 8) | ((nc ^ row) & 7);
            cp_async16(smem + 8192 + row * 256 + csw * 16,
                       g_w1b + (size_t)row * 256 + nc * 16);
        }
        asm volatile("cp.async.commit_group;" ::: "memory");
        float4 v0 = *(const float4*)xr;
        float4 v1 = *(const float4*)(xr + 4);
        uint4 p;
        p.x = packbf2(v0.x, v0.y); p.y = packbf2(v0.z, v0.w);
        p.z = packbf2(v1.x, v1.y); p.w = packbf2(v1.z, v1.w);
        *(uint4*)(smem + As_row * 128 + As_csw * 16) = p;
        asm volatile("cp.async.wait_group 0;" ::: "memory");
        __syncthreads();
    }

    const int mw = warp & 1;           // m16 tile
    const int nv = warp >> 1;          // n32 group (0..3)
    const int arow = mw * 16 + (lane & 15);
    const int ar7 = arow & 7;
    const int brow16 = lane & 15;
    const int bhi = lane >> 4;

    float d[4][4];
#pragma unroll
    for (int t = 0; t < 4; t++)
#pragma unroll
        for (int j = 0; j < 4; j++) d[t][j] = 0.0f;

    float4 pv0, pv1;
    for (int kt = 0; kt < 12; kt++) {
        const uint32_t abuf = (kt & 1) * 4096;
        const uint32_t bbuf = 8192 + (kt & 1) * 16384;

        if (kt < 11) {
            const unsigned char* wb = g_w1b + (size_t)(kt + 1) * 64 * 256;
            unsigned char* bd = smem + 8192 + ((kt + 1) & 1) * 16384;
#pragma unroll
            for (int i = 0; i < 4; i++) {
                int c = tid + 256 * i;
                int row = c >> 4, nc = c & 15;
                int csw = (nc & 8) | ((nc ^ row) & 7);
                cp_async16(bd + row * 256 + csw * 16,
                           wb + (size_t)row * 256 + nc * 16);
            }
            asm volatile("cp.async.commit_group;" ::: "memory");
            pv0 = *(const float4*)(xr + (kt + 1) * 64);
            pv1 = *(const float4*)(xr + (kt + 1) * 64 + 4);
        }

#pragma unroll
        for (int ks = 0; ks < 4; ks++) {
            uint32_t a0, a1, a2, a3;
            {
                int chunk = ks * 2 + bhi;
                int csw = (chunk ^ ar7) & 7;
                ldsm_x4(a0, a1, a2, a3, sbase + abuf + arow * 128 + csw * 16);
            }
            int brow = ks * 16 + brow16;
            uint32_t braddr = sbase + bbuf + brow * 256;
            int br7 = brow & 7;
#pragma unroll
            for (int ntp = 0; ntp < 2; ntp++) {
                uint32_t b0, b1r, b2, b3;
                int chunk = nv * 4 + ntp * 2 + bhi;
                int csw = (chunk & 8) | ((chunk ^ br7) & 7);
                ldsm_x4t(b0, b1r, b2, b3, braddr + csw * 16);
                mma_bf16(d[2 * ntp],     a0, a1, a2, a3, b0, b1r);
                mma_bf16(d[2 * ntp + 1], a0, a1, a2, a3, b2, b3);
            }
        }

        if (kt < 11) {
            uint4 p;
            p.x = packbf2(pv0.x, pv0.y); p.y = packbf2(pv0.z, pv0.w);
            p.z = packbf2(pv1.x, pv1.y); p.w = packbf2(pv1.z, pv1.w);
            *(uint4*)(smem + (((kt + 1) & 1) * 4096) + As_row * 128 + As_csw * 16) = p;
            asm volatile("cp.async.wait_group 0;" ::: "memory");
            __syncthreads();
        }
    }
    __syncthreads();   // all warps done with A/B smem

    // ---- acc(+b1) -> h tile in smem (reuse A/B region) ----
    float* h_s = (float*)smem;                    // 32 x 133 (17024 B)
    float* rk_s = (float*)(smem + 17408);         // [64][36]  (9216 B)
    {
        int r = mw * 16 + (lane >> 2);
#pragma unroll
        for (int nt = 0; nt < 4; nt++) {
            int col = nv * 32 + nt * 8 + 2 * (lane & 3);
            h_s[r * 133 + col]           = d[nt][0] + b1s[col];
            h_s[r * 133 + col + 1]       = d[nt][1] + b1s[col + 1];
            h_s[(r + 8) * 133 + col]     = d[nt][2] + b1s[col];
            h_s[(r + 8) * 133 + col + 1] = d[nt][3] + b1s[col + 1];
        }
    }
    __syncthreads();

    // ---- RoPE: q -> g_qb direct (coalesced bf16 pairs), k -> rk_s tile ----
    const int tn = tid & 31;
    const int tmw = tid >> 5;
    const int b = row0 >> 10;
    const int s0 = row0 & 1023;
    const float invfe = invf_s[(2 * tn) & 31];
    const float invfo = invf_s[(2 * tn + 1) & 31];
    uint32_t* qb32 = (uint32_t*)g_qb + (size_t)b * 1024 * 32;

#pragma unroll
    for (int mi = 0; mi < 4; mi++) {
        int r = 4 * tmw + mi;
        float h0 = h_s[r * 133 + 4 * tn + 0];
        float h1 = h_s[r * 133 + 4 * tn + 1];
        float h2 = h_s[r * 133 + 4 * tn + 2];
        float h3 = h_s[r * 133 + 4 * tn + 3];

        float fs = (float)(s0 + r);
        float se, ce, so, co;
        sincosf(fs * invfe, &se, &ce);
        sincosf(fs * invfo, &so, &co);

        float qe = (h0 * ce - h2 * se) * 0.125f;   // fold 1/sqrt(64) into q
        float qo = (h2 * co + h0 * so) * 0.125f;
        qb32[(size_t)(s0 + r) * 32 + tn] = packbf2(qe, qo);
        rk_s[(2 * tn) * 36 + r]     = h1 * ce - h3 * se;
        rk_s[(2 * tn + 1) * 36 + r] = h3 * co + h1 * so;
    }
    __syncthreads();

    // ---- coalesced k writeback: thread -> dim dd = tid>>2, 8 bf16 ----
    {
        int dd = tid >> 2, ch = tid & 3;
        const float* src = &rk_s[dd * 36 + ch * 8];
        uint4 p;
        p.x = packbf2(src[0], src[1]);
        p.y = packbf2(src[2], src[3]);
        p.z = packbf2(src[4], src[5]);
        p.w = packbf2(src[6], src[7]);
        *(uint4*)(g_kb + (((size_t)(b * 64 + dd)) * 1024 + s0 + ch * 8) * 2) = p;
    }

    // ---- bias GEMM: h @ W2 + b2 ----
    {
        const int r = tid & 31;
        const int hb4 = (tid >> 5) * 4;
        float4 accb = *(const float4*)(b2 + hb4);
        const float* hp = h_s + r * 133;
#pragma unroll 8
        for (int kk = 0; kk < 128; kk++) {
            float hv = hp[kk];
            float4 wv = *(const float4*)(W2 + kk * 32 + hb4);
            accb.x += hv * wv.x;
            accb.y += hv * wv.y;
            accb.z += hv * wv.z;
            accb.w += hv * wv.w;
        }
        int s = s0 + r;
        float vals[4] = {accb.x * 0.5f, accb.y * 0.5f, accb.z * 0.5f, accb.w * 0.5f};
#pragma unroll
        for (int j = 0; j < 4; j++) {
            int ho = hb4 + j;
            int o = ho >> 1;
            if (ho & 1) g_bB[(size_t)(b * 16 + o) * 1024 + s] = vals[j];
            else        g_bA[(size_t)(b * 16 + o) * 1024 + s] = vals[j];
        }
    }
}

// ---------------- kernel 2: logits via mma.sync dots (R14, unchanged) --------
__global__ __launch_bounds__(256) void k2_kernel(const float* __restrict__ mask,
                                                 float* __restrict__ out) {
    __shared__ __align__(16) unsigned char smem[30720];
    const uint32_t sbase = (uint32_t)__cvta_generic_to_shared(smem);
    float* bA_s = (float*)(smem + 20480);
    float* bB_s = (float*)(smem + 28672);

    const int tid = threadIdx.x;
    const int lane = tid & 31;
    const int warp = tid >> 5;
    const int tn = tid & 31;
    const int tm = tid >> 5;
    const int b = blockIdx.z;
    const int m0 = blockIdx.y * 32;
    const int n0 = blockIdx.x * 128;

    // ---- stage all tiles via cp.async ----
    {
        int row = tid >> 3, nc = tid & 7;
        int csw = (nc ^ (row & 7)) & 7;
        cp_async16(smem + row * 128 + csw * 16,
                   g_qb + ((size_t)(b * 1024 + m0 + row) * 64) * 2 + nc * 16);
#pragma unroll
        for (int i = 0; i < 4; i++) {
            int c = tid + 256 * i;
            int krow = c >> 4, knc = c & 15;
            int kcsw = (knc & 8) | ((knc ^ krow) & 7);
            cp_async16(smem + 4096 + krow * 256 + kcsw * 16,
                       g_kb + ((size_t)(b * 64 + krow) * 1024 + n0) * 2 + knc * 16);
        }
        const float* bAg = g_bA + (size_t)(b * 16) * 1024 + n0;
#pragma unroll
        for (int i = 0; i < 2; i++) {
            int f = tid + 256 * i;
            int o = f >> 5, col = (f & 31) * 4;
            cp_async16(&bA_s[o * 128 + col], bAg + o * 1024 + col);
        }
        if (tid < 128) {
            const float* bBg = g_bB + (size_t)(b * 16) * 1024 + m0;
            int o = tid >> 3, col = (tid & 7) * 4;
            cp_async16(&bB_s[o * 32 + col], bBg + o * 1024 + col);
        }
        asm volatile("cp.async.commit_group;" ::: "memory");
        asm volatile("cp.async.wait_group 0;" ::: "memory");
        __syncthreads();
    }

    // ---- dot via mma.sync (K=64 single stage) ----
    const int mw = warp & 1;
    const int nv = warp >> 1;
    const int arow = mw * 16 + (lane & 15);
    const int ar7 = arow & 7;
    const int brow16 = lane & 15;
    const int bhi = lane >> 4;

    float d[4][4];
#pragma unroll
    for (int t = 0; t < 4; t++)
#pragma unroll
        for (int j = 0; j < 4; j++) d[t][j] = 0.0f;

#pragma unroll
    for (int ks = 0; ks < 4; ks++) {
        uint32_t a0, a1, a2, a3;
        {
            int chunk = ks * 2 + bhi;
            int csw = (chunk ^ ar7) & 7;
            ldsm_x4(a0, a1, a2, a3, sbase + arow * 128 + csw * 16);
        }
        int brow = ks * 16 + brow16;
        uint32_t braddr = sbase + 4096 + brow * 256;
        int br7 = brow & 7;
#pragma unroll
        for (int ntp = 0; ntp < 2; ntp++) {
            uint32_t b0, b1r, b2, b3;
            int chunk = nv * 4 + ntp * 2 + bhi;
            int csw = (chunk & 8) | ((chunk ^ br7) & 7);
            ldsm_x4t(b0, b1r, b2, b3, braddr + csw * 16);
            mma_bf16(d[2 * ntp],     a0, a1, a2, a3, b0, b1r);
            mma_bf16(d[2 * ntp + 1], a0, a1, a2, a3, b2, b3);
        }
    }
    __syncthreads();

    // ---- dots -> d_s (overlay) in [m][n] layout ----
    float* d_s = (float*)smem;
    {
        int r0 = mw * 16 + (lane >> 2);
        int c0 = 2 * (lane & 3);
#pragma unroll
        for (int nt = 0; nt < 4; nt++) {
            int col = nv * 32 + nt * 8 + c0;
            *(float2*)&d_s[r0 * 132 + col] = make_float2(d[nt][0], d[nt][1]);
            *(float2*)&d_s[(r0 + 8) * 132 + col] = make_float2(d[nt][2], d[nt][3]);
        }
    }
    __syncthreads();

    const int nbase = n0 + 4 * tn;
    const int mbase = m0 + 4 * tm;

    float d0[4][4];
#pragma unroll
    for (int mi = 0; mi < 4; mi++) {
        float4 v = *(const float4*)&d_s[(4 * tm + mi) * 132 + 4 * tn];
        d0[mi][0] = v.x; d0[mi][1] = v.y; d0[mi][2] = v.z; d0[mi][3] = v.w;
    }

    float pm[4];
    {
        float4 mv = *(const float4*)(mask + b * 1024 + nbase);
        pm[0] = mv.x; pm[1] = mv.y; pm[2] = mv.z; pm[3] = mv.w;
    }
    unsigned long long pm2[2] = {pk2(pm[0], pm[1]), pk2(pm[2], pm[3])};

    unsigned long long dpm2[4][2];
#pragma unroll
    for (int mi = 0; mi < 4; mi++) {
        int mg = mbase + mi;
        float c0 = -(1.0f - pm[0]) * NEGV - (mg > nbase + 0 ? NEGV : 0.0f);
        float c1 = -(1.0f - pm[1]) * NEGV - (mg > nbase + 1 ? NEGV : 0.0f);
        float c2 = -(1.0f - pm[2]) * NEGV - (mg > nbase + 2 ? NEGV : 0.0f);
        float c3 = -(1.0f - pm[3]) * NEGV - (mg > nbase + 3 ? NEGV : 0.0f);
        dpm2[mi][0] = pk2(fmaf(d0[mi][0], pm[0], c0), fmaf(d0[mi][1], pm[1], c1));
        dpm2[mi][1] = pk2(fmaf(d0[mi][2], pm[2], c2), fmaf(d0[mi][3], pm[3], c3));
    }

    float* op0 = out + ((size_t)(b * 16) * 1024 + mbase) * 1024 + nbase;

#pragma unroll 4
    for (int o = 0; o < 16; o++) {
        float4 ba = *(const float4*)&bA_s[o * 128 + 4 * tn];
        float4 bb = *(const float4*)&bB_s[o * 32 + 4 * tm];
        unsigned long long ba2[2] = {pk2(ba.x, ba.y), pk2(ba.z, ba.w)};
        float bbv[4] = {bb.x, bb.y, bb.z, bb.w};
        float* op = op0 + (size_t)o * 1024 * 1024;
#pragma unroll
        for (int mi = 0; mi < 4; mi++) {
            unsigned long long bb2 = pk2(bbv[mi], bbv[mi]);
            unsigned long long v0 = fma2n(add2(ba2[0], bb2), pm2[0], dpm2[mi][0]);
            unsigned long long v1 = fma2n(add2(ba2[1], bb2), pm2[1], dpm2[mi][1]);
            float2 r0 = up2(v0);
            float2 r1 = up2(v1);
            float4 r = make_float4(r0.x, r0.y, r1.x, r1.y);
            __stcs((float4*)(op + (size_t)mi * 1024), r);
        }
    }
}

extern "C" void kernel_launch(void* const* d_in, const int* in_sizes, int n_in,
                              void* d_out, int out_size) {
    const float* x    = (const float*)d_in[0];  // (4,1024,768)
    const float* mask = (const float*)d_in[1];  // (4,1024)
    const float* W1   = (const float*)d_in[2];  // (768,128)
    const float* b1   = (const float*)d_in[3];  // (128)
    const float* W2   = (const float*)d_in[4];  // (128,32)
    const float* b2   = (const float*)d_in[5];  // (32)
    float* out = (float*)d_out;                 // (4,16,1024,1024)

    k1_kernel<<<128, 256>>>(x, W1, b1, W2, b2);
    k2_kernel<<<dim3(8, 32, 4), 256>>>(mask, out);
}

// round 17
// speedup vs baseline: 1.0026x; 1.0026x over previous
#include <cuda_runtime.h>
#include <cuda_bf16.h>
#include <cstdint>
#include <math.h>

#define NEGV 1000000000000.0f

// ---------------- scratch (static device globals; no allocs) ----------------
__device__ __align__(16) unsigned char g_w1b[768 * 128 * 2];  // W1 bf16 row-major
__device__ __align__(16) unsigned char g_qb[4 * 1024 * 64 * 2]; // q bf16 [b][m][d], pre-scaled 1/8
__device__ __align__(16) unsigned char g_kb[4 * 64 * 1024 * 2]; // k bf16 [b][d][n]
__device__ float g_bA[4 * 16 * 1024];    // bias[b, n, 2o]/2   -> indexed [b][o][n]
__device__ float g_bB[4 * 16 * 1024];    // bias[b, m, 2o+1]/2 -> indexed [b][o][m]

// ---------------- packed f32x2 helpers ----------------
__device__ __forceinline__ unsigned long long pk2(float lo, float hi) {
    unsigned long long r;
    asm("mov.b64 %0, {%1,%2};" : "=l"(r) : "f"(lo), "f"(hi));
    return r;
}
__device__ __forceinline__ unsigned long long fma2n(unsigned long long a,
                                                    unsigned long long b,
                                                    unsigned long long c) {
    unsigned long long d;
    asm("fma.rn.f32x2 %0, %1, %2, %3;" : "=l"(d) : "l"(a), "l"(b), "l"(c));
    return d;
}
__device__ __forceinline__ unsigned long long add2(unsigned long long a,
                                                   unsigned long long b) {
    unsigned long long d;
    asm("add.rn.f32x2 %0, %1, %2;" : "=l"(d) : "l"(a), "l"(b));
    return d;
}
__device__ __forceinline__ float2 up2(unsigned long long v) {
    float2 r;
    asm("mov.b64 {%0,%1}, %2;" : "=f"(r.x), "=f"(r.y) : "l"(v));
    return r;
}
__device__ __forceinline__ void cp_async16(void* smem_dst, const void* gsrc) {
    unsigned saddr = (unsigned)__cvta_generic_to_shared(smem_dst);
    asm volatile("cp.async.ca.shared.global [%0], [%1], 16;\n"
                 :: "r"(saddr), "l"(gsrc) : "memory");
}
__device__ __forceinline__ uint32_t packbf2(float a, float b) {
    __nv_bfloat162 v = __floats2bfloat162_rn(a, b);
    return *(uint32_t*)&v;
}
__device__ __forceinline__ void ldsm_x4(uint32_t& r0, uint32_t& r1, uint32_t& r2,
                                        uint32_t& r3, uint32_t addr) {
    asm volatile("ldmatrix.sync.aligned.m8n8.x4.shared.b16 {%0,%1,%2,%3}, [%4];"
                 : "=r"(r0), "=r"(r1), "=r"(r2), "=r"(r3) : "r"(addr));
}
__device__ __forceinline__ void ldsm_x4t(uint32_t& r0, uint32_t& r1, uint32_t& r2,
                                         uint32_t& r3, uint32_t addr) {
    asm volatile("ldmatrix.sync.aligned.m8n8.x4.trans.shared.b16 {%0,%1,%2,%3}, [%4];"
                 : "=r"(r0), "=r"(r1), "=r"(r2), "=r"(r3) : "r"(addr));
}
__device__ __forceinline__ void mma_bf16(float* d, uint32_t a0, uint32_t a1,
                                         uint32_t a2, uint32_t a3, uint32_t b0,
                                         uint32_t b1) {
    asm volatile(
        "mma.sync.aligned.m16n8k16.row.col.f32.bf16.bf16.f32 "
        "{%0,%1,%2,%3}, {%4,%5,%6,%7}, {%8,%9}, {%0,%1,%2,%3};"
        : "+f"(d[0]), "+f"(d[1]), "+f"(d[2]), "+f"(d[3])
        : "r"(a0), "r"(a1), "r"(a2), "r"(a3), "r"(b0), "r"(b1));
}

// ---------------- prep: W1 -> bf16 row-major ----------------
__global__ __launch_bounds__(256) void prep_w1_kernel(const float* __restrict__ W1) {
    int i = (blockIdx.x * 256 + threadIdx.x) * 4;   // 98304 elements
    float4 v = *(const float4*)(W1 + i);
    uint2 p;
    p.x = packbf2(v.x, v.y);
    p.y = packbf2(v.z, v.w);
    *(uint2*)(g_w1b + (size_t)i * 2) = p;
}

// ---------------- kernel 1 (fused): h = x@W1+b1 -> RoPE (bf16) + bias -------
// (R14 version, byte-identical — 128 blocks, 256 thr, 12 x BK=64 stages)
__global__ __launch_bounds__(256) void k1_kernel(
    const float* __restrict__ x, const float* __restrict__ b1,
    const float* __restrict__ W2, const float* __restrict__ b2) {
    __shared__ __align__(16) unsigned char smem[41600];
    const uint32_t sbase = (uint32_t)__cvta_generic_to_shared(smem);
    float* b1s = (float*)(smem + 40960);
    float* invf_s = (float*)(smem + 41472);

    const int tid = threadIdx.x;
    const int lane = tid & 31;
    const int warp = tid >> 5;
    const int row0 = blockIdx.x * 32;

    if (tid < 128) b1s[tid] = b1[tid];
    else if (tid < 160) {
        int j = tid - 128;
        invf_s[j] = (float)exp(-(double)j * (9.210340371976184 / 32.0));
    }

    const int As_row = tid >> 3;       // 0..31
    const int As_kc = tid & 7;         // 0..7
    const int As_csw = (As_kc ^ (As_row & 7)) & 7;
    const float* xr = x + (size_t)(row0 + As_row) * 768 + As_kc * 8;

    // ---- prologue: stage kt=0 ----
    {
#pragma unroll
        for (int i = 0; i < 4; i++) {
            int c = tid + 256 * i;             // 1024 chunks
            int row = c >> 4, nc = c & 15;
            int csw = (nc & 8) | ((nc ^ row) & 7);
            cp_async16(smem + 8192 + row * 256 + csw * 16,
                       g_w1b + (size_t)row * 256 + nc * 16);
        }
        asm volatile("cp.async.commit_group;" ::: "memory");
        float4 v0 = *(const float4*)xr;
        float4 v1 = *(const float4*)(xr + 4);
        uint4 p;
        p.x = packbf2(v0.x, v0.y); p.y = packbf2(v0.z, v0.w);
        p.z = packbf2(v1.x, v1.y); p.w = packbf2(v1.z, v1.w);
        *(uint4*)(smem + As_row * 128 + As_csw * 16) = p;
        asm volatile("cp.async.wait_group 0;" ::: "memory");
        __syncthreads();
    }

    const int mw = warp & 1;           // m16 tile
    const int nv = warp >> 1;          // n32 group (0..3)
    const int arow = mw * 16 + (lane & 15);
    const int ar7 = arow & 7;
    const int brow16 = lane & 15;
    const int bhi = lane >> 4;

    float d[4][4];
#pragma unroll
    for (int t = 0; t < 4; t++)
#pragma unroll
        for (int j = 0; j < 4; j++) d[t][j] = 0.0f;

    float4 pv0, pv1;
    for (int kt = 0; kt < 12; kt++) {
        const uint32_t abuf = (kt & 1) * 4096;
        const uint32_t bbuf = 8192 + (kt & 1) * 16384;

        if (kt < 11) {
            const unsigned char* wb = g_w1b + (size_t)(kt + 1) * 64 * 256;
            unsigned char* bd = smem + 8192 + ((kt + 1) & 1) * 16384;
#pragma unroll
            for (int i = 0; i < 4; i++) {
                int c = tid + 256 * i;
                int row = c >> 4, nc = c & 15;
                int csw = (nc & 8) | ((nc ^ row) & 7);
                cp_async16(bd + row * 256 + csw * 16,
                           wb + (size_t)row * 256 + nc * 16);
            }
            asm volatile("cp.async.commit_group;" ::: "memory");
            pv0 = *(const float4*)(xr + (kt + 1) * 64);
            pv1 = *(const float4*)(xr + (kt + 1) * 64 + 4);
        }

#pragma unroll
        for (int ks = 0; ks < 4; ks++) {
            uint32_t a0, a1, a2, a3;
            {
                int chunk = ks * 2 + bhi;
                int csw = (chunk ^ ar7) & 7;
                ldsm_x4(a0, a1, a2, a3, sbase + abuf + arow * 128 + csw * 16);
            }
            int brow = ks * 16 + brow16;
            uint32_t braddr = sbase + bbuf + brow * 256;
            int br7 = brow & 7;
#pragma unroll
            for (int ntp = 0; ntp < 2; ntp++) {
                uint32_t b0, b1r, b2, b3;
                int chunk = nv * 4 + ntp * 2 + bhi;
                int csw = (chunk & 8) | ((chunk ^ br7) & 7);
                ldsm_x4t(b0, b1r, b2, b3, braddr + csw * 16);
                mma_bf16(d[2 * ntp],     a0, a1, a2, a3, b0, b1r);
                mma_bf16(d[2 * ntp + 1], a0, a1, a2, a3, b2, b3);
            }
        }

        if (kt < 11) {
            uint4 p;
            p.x = packbf2(pv0.x, pv0.y); p.y = packbf2(pv0.z, pv0.w);
            p.z = packbf2(pv1.x, pv1.y); p.w = packbf2(pv1.z, pv1.w);
            *(uint4*)(smem + (((kt + 1) & 1) * 4096) + As_row * 128 + As_csw * 16) = p;
            asm volatile("cp.async.wait_group 0;" ::: "memory");
            __syncthreads();
        }
    }
    __syncthreads();   // all warps done with A/B smem

    // ---- acc(+b1) -> h tile in smem (reuse A/B region) ----
    float* h_s = (float*)smem;                    // 32 x 133 (17024 B)
    float* rk_s = (float*)(smem + 17408);         // [64][36]  (9216 B)
    {
        int r = mw * 16 + (lane >> 2);
#pragma unroll
        for (int nt = 0; nt < 4; nt++) {
            int col = nv * 32 + nt * 8 + 2 * (lane & 3);
            h_s[r * 133 + col]           = d[nt][0] + b1s[col];
            h_s[r * 133 + col + 1]       = d[nt][1] + b1s[col + 1];
            h_s[(r + 8) * 133 + col]     = d[nt][2] + b1s[col];
            h_s[(r + 8) * 133 + col + 1] = d[nt][3] + b1s[col + 1];
        }
    }
    __syncthreads();

    // ---- RoPE: q -> g_qb direct (coalesced bf16 pairs), k -> rk_s tile ----
    const int tn = tid & 31;
    const int tmw = tid >> 5;
    const int b = row0 >> 10;
    const int s0 = row0 & 1023;
    const float invfe = invf_s[(2 * tn) & 31];
    const float invfo = invf_s[(2 * tn + 1) & 31];
    uint32_t* qb32 = (uint32_t*)g_qb + (size_t)b * 1024 * 32;

#pragma unroll
    for (int mi = 0; mi < 4; mi++) {
        int r = 4 * tmw + mi;
        float h0 = h_s[r * 133 + 4 * tn + 0];
        float h1 = h_s[r * 133 + 4 * tn + 1];
        float h2 = h_s[r * 133 + 4 * tn + 2];
        float h3 = h_s[r * 133 + 4 * tn + 3];

        float fs = (float)(s0 + r);
        float se, ce, so, co;
        sincosf(fs * invfe, &se, &ce);
        sincosf(fs * invfo, &so, &co);

        float qe = (h0 * ce - h2 * se) * 0.125f;   // fold 1/sqrt(64) into q
        float qo = (h2 * co + h0 * so) * 0.125f;
        qb32[(size_t)(s0 + r) * 32 + tn] = packbf2(qe, qo);
        rk_s[(2 * tn) * 36 + r]     = h1 * ce - h3 * se;
        rk_s[(2 * tn + 1) * 36 + r] = h3 * co + h1 * so;
    }
    __syncthreads();

    // ---- coalesced k writeback: thread -> dim dd = tid>>2, 8 bf16 ----
    {
        int dd = tid >> 2, ch = tid & 3;
        const float* src = &rk_s[dd * 36 + ch * 8];
        uint4 p;
        p.x = packbf2(src[0], src[1]);
        p.y = packbf2(src[2], src[3]);
        p.z = packbf2(src[4], src[5]);
        p.w = packbf2(src[6], src[7]);
        *(uint4*)(g_kb + (((size_t)(b * 64 + dd)) * 1024 + s0 + ch * 8) * 2) = p;
    }

    // ---- bias GEMM: h @ W2 + b2 ----
    {
        const int r = tid & 31;
        const int hb4 = (tid >> 5) * 4;
        float4 accb = *(const float4*)(b2 + hb4);
        const float* hp = h_s + r * 133;
#pragma unroll 8
        for (int kk = 0; kk < 128; kk++) {
            float hv = hp[kk];
            float4 wv = *(const float4*)(W2 + kk * 32 + hb4);
            accb.x += hv * wv.x;
            accb.y += hv * wv.y;
            accb.z += hv * wv.z;
            accb.w += hv * wv.w;
        }
        int s = s0 + r;
        float vals[4] = {accb.x * 0.5f, accb.y * 0.5f, accb.z * 0.5f, accb.w * 0.5f};
#pragma unroll
        for (int j = 0; j < 4; j++) {
            int ho = hb4 + j;
            int o = ho >> 1;
            if (ho & 1) g_bB[(size_t)(b * 16 + o) * 1024 + s] = vals[j];
            else        g_bA[(size_t)(b * 16 + o) * 1024 + s] = vals[j];
        }
    }
}

// ---------------- kernel 2: logits, 64m x 128n tiles ----------------
// Grid (8, 16, 4) = 512 blocks, 256 thr. Dot via R12-verified 4-m-tile mma.
// smem (36864B): q_s bf16 64x128B @0 (8KB), k_s bf16 64x256B @8192 (16KB),
//   bA_s [16][128] @24576 (8KB), bB_s [16][64] @32768 (4KB).
// d_s fp32 32x132 (16.9KB) overlays q_s/k_s per 32-row epilogue pass.
__global__ __launch_bounds__(256) void k2_kernel(const float* __restrict__ mask,
                                                 float* __restrict__ out) {
    __shared__ __align__(16) unsigned char smem[36864];
    const uint32_t sbase = (uint32_t)__cvta_generic_to_shared(smem);
    float* bA_s = (float*)(smem + 24576);
    float* bB_s = (float*)(smem + 32768);

    const int tid = threadIdx.x;
    const int lane = tid & 31;
    const int warp = tid >> 5;
    const int tn = tid & 31;
    const int tm = tid >> 5;
    const int b = blockIdx.z;
    const int m0 = blockIdx.y * 64;
    const int n0 = blockIdx.x * 128;

    // ---- stage all tiles via cp.async ----
    {
#pragma unroll
        for (int i = 0; i < 2; i++) {           // q: 512 chunks (64 rows x 8)
            int c = tid + 256 * i;
            int row = c >> 3, nc = c & 7;
            int csw = (nc ^ (row & 7)) & 7;
            cp_async16(smem + row * 128 + csw * 16,
                       g_qb + ((size_t)(b * 1024 + m0 + row) * 64) * 2 + nc * 16);
        }
#pragma unroll
        for (int i = 0; i < 4; i++) {           // k: 1024 chunks (64 d x 16)
            int c = tid + 256 * i;
            int krow = c >> 4, knc = c & 15;
            int kcsw = (knc & 8) | ((knc ^ krow) & 7);
            cp_async16(smem + 8192 + krow * 256 + kcsw * 16,
                       g_kb + ((size_t)(b * 64 + krow) * 1024 + n0) * 2 + knc * 16);
        }
        const float* bAg = g_bA + (size_t)(b * 16) * 1024 + n0;
#pragma unroll
        for (int i = 0; i < 2; i++) {           // bA: 512 chunks
            int f = tid + 256 * i;
            int o = f >> 5, col = (f & 31) * 4;
            cp_async16(&bA_s[o * 128 + col], bAg + o * 1024 + col);
        }
        {                                       // bB: 256 chunks (16 o x 16)
            const float* bBg = g_bB + (size_t)(b * 16) * 1024 + m0;
            int o = tid >> 4, col = (tid & 15) * 4;
            cp_async16(&bB_s[o * 64 + col], bBg + o * 1024 + col);
        }
        asm volatile("cp.async.commit_group;" ::: "memory");
        asm volatile("cp.async.wait_group 0;" ::: "memory");
        __syncthreads();
    }

    // ---- dot via mma.sync: warp = m16 x n64 (mw = warp&3, nv = warp>>2) ----
    const int mw = warp & 3;
    const int nv = warp >> 2;
    const int arow = mw * 16 + (lane & 15);
    const int ar7 = arow & 7;
    const int brow16 = lane & 15;
    const int bhi = lane >> 4;

    float d[8][4];
#pragma unroll
    for (int t = 0; t < 8; t++)
#pragma unroll
        for (int j = 0; j < 4; j++) d[t][j] = 0.0f;

#pragma unroll
    for (int ks = 0; ks < 4; ks++) {
        uint32_t a0, a1, a2, a3;
        {
            int chunk = ks * 2 + bhi;
            int csw = (chunk ^ ar7) & 7;
            ldsm_x4(a0, a1, a2, a3, sbase + arow * 128 + csw * 16);
        }
        int brow = ks * 16 + brow16;
        uint32_t braddr = sbase + 8192 + brow * 256;
        int br7 = brow & 7;
#pragma unroll
        for (int ntp = 0; ntp < 4; ntp++) {
            uint32_t b0, b1r, b2, b3;
            int chunk = nv * 8 + ntp * 2 + bhi;
            int csw = (chunk & 8) | ((chunk ^ br7) & 7);
            ldsm_x4t(b0, b1r, b2, b3, braddr + csw * 16);
            mma_bf16(d[2 * ntp],     a0, a1, a2, a3, b0, b1r);
            mma_bf16(d[2 * ntp + 1], a0, a1, a2, a3, b2, b3);
        }
    }
    __syncthreads();   // done reading q_s/k_s

    float* d_s = (float*)smem;          // 32 x 132 fp32 overlay
    const int nbase = n0 + 4 * tn;

    float pm[4];
    {
        float4 mv = *(const float4*)(mask + b * 1024 + nbase);
        pm[0] = mv.x; pm[1] = mv.y; pm[2] = mv.z; pm[3] = mv.w;
    }
    unsigned long long pm2[2] = {pk2(pm[0], pm[1]), pk2(pm[2], pm[3])};
    const float pen0 = -(1.0f - pm[0]) * NEGV;
    const float pen1 = -(1.0f - pm[1]) * NEGV;
    const float pen2 = -(1.0f - pm[2]) * NEGV;
    const float pen3 = -(1.0f - pm[3]) * NEGV;

    // ---- two epilogue passes of 32 m-rows each ----
#pragma unroll
    for (int p = 0; p < 2; p++) {
        // fragments -> d_s (warps whose m16 tiles fall in this 32-row half)
        if ((mw >> 1) == p) {
            int r0 = (mw & 1) * 16 + (lane >> 2);
            int c0 = 2 * (lane & 3);
#pragma unroll
            for (int nt = 0; nt < 8; nt++) {
                int col = nv * 64 + nt * 8 + c0;
                *(float2*)&d_s[r0 * 132 + col] = make_float2(d[nt][0], d[nt][1]);
                *(float2*)&d_s[(r0 + 8) * 132 + col] = make_float2(d[nt][2], d[nt][3]);
            }
        }
        __syncthreads();

        const int mbase = m0 + p * 32 + 4 * tm;

        float d0[4][4];
#pragma unroll
        for (int mi = 0; mi < 4; mi++) {
            float4 v = *(const float4*)&d_s[(4 * tm + mi) * 132 + 4 * tn];
            d0[mi][0] = v.x; d0[mi][1] = v.y; d0[mi][2] = v.z; d0[mi][3] = v.w;
        }

        unsigned long long dpm2[4][2];
#pragma unroll
        for (int mi = 0; mi < 4; mi++) {
            int mg = mbase + mi;
            float c0 = pen0 - (mg > nbase + 0 ? NEGV : 0.0f);
            float c1 = pen1 - (mg > nbase + 1 ? NEGV : 0.0f);
            float c2 = pen2 - (mg > nbase + 2 ? NEGV : 0.0f);
            float c3 = pen3 - (mg > nbase + 3 ? NEGV : 0.0f);
            dpm2[mi][0] = pk2(fmaf(d0[mi][0], pm[0], c0), fmaf(d0[mi][1], pm[1], c1));
            dpm2[mi][1] = pk2(fmaf(d0[mi][2], pm[2], c2), fmaf(d0[mi][3], pm[3], c3));
        }

        float* op0 = out + ((size_t)(b * 16) * 1024 + mbase) * 1024 + nbase;
        const int bBoff = p * 32 + 4 * tm;

#pragma unroll 4
        for (int o = 0; o < 16; o++) {
            float4 ba = *(const float4*)&bA_s[o * 128 + 4 * tn];
            float4 bb = *(const float4*)&bB_s[o * 64 + bBoff];
            unsigned long long ba2[2] = {pk2(ba.x, ba.y), pk2(ba.z, ba.w)};
            float bbv[4] = {bb.x, bb.y, bb.z, bb.w};
            float* op = op0 + (size_t)o * 1024 * 1024;
#pragma unroll
            for (int mi = 0; mi < 4; mi++) {
                unsigned long long bb2 = pk2(bbv[mi], bbv[mi]);
                unsigned long long v0 = fma2n(add2(ba2[0], bb2), pm2[0], dpm2[mi][0]);
                unsigned long long v1 = fma2n(add2(ba2[1], bb2), pm2[1], dpm2[mi][1]);
                float2 r0 = up2(v0);
                float2 r1 = up2(v1);
                float4 r = make_float4(r0.x, r0.y, r1.x, r1.y);
                __stcs((float4*)(op + (size_t)mi * 1024), r);
            }
        }
        __syncthreads();   // d_s reused by next pass
    }
}

extern "C" void kernel_launch(void* const* d_in, const int* in_sizes, int n_in,
                              void* d_out, int out_size) {
    const float* x    = (const float*)d_in[0];  // (4,1024,768)
    const float* mask = (const float*)d_in[1];  // (4,1024)
    const float* W1   = (const float*)d_in[2];  // (768,128)
    const float* b1   = (const float*)d_in[3];  // (128)
    const float* W2   = (const float*)d_in[4];  // (128,32)
    const float* b2   = (const float*)d_in[5];  // (32)
    float* out = (float*)d_out;                 // (4,16,1024,1024)

    prep_w1_kernel<<<96, 256>>>(W1);
    k1_kernel<<<128, 256>>>(x, b1, W2, b2);
    k2_kernel<<<dim3(8, 16, 4), 256>>>(mask, out);
}